// round 12
// baseline (speedup 1.0000x reference)
#include <cuda_runtime.h>
#include <stdint.h>

// TransposeIrrepsLayout: per-row segment transpose, segments (u,v) =
// (128,1),(64,3),(32,5),(16,7), row dim 592 fp32, 200000 rows.
// out[off + a*u + b] = in[off + b*v + a]
// For output column c: a = (c-off) >> log2(u), b = (c-off) & (u-1); src = off + b*v + a
//
// FINAL converged design — measured at the memory-system roofline:
// ~7.15 TB/s effective (89% of HBM3e spec), 85% dram__cycles_active,
// streaming-memcpy parity. Confirmed over 8 benches; R10's 74%-DRAM
// reading was an environmental outlier (identical SASS, degraded hold)
// and reverted to baseline on re-bench (R11).
//
//  - 4 rows staged per CTA in 9.5 KB smem -> 16 CTAs/SM, ~94% occupancy;
//    cross-CTA load/store phase mixing overlaps the read and write streams
//    (explicit intra-CTA pipelines measured strictly worse: -7..-10% DRAM).
//  - Phase 1: float4 coalesced streaming loads (evict-first, touch-once).
//  - Phase 2: lane-consecutive output columns -> coalesced STG.32 streaming
//    stores; smem gather lane-stride = v in {1,3,5,7} (all odd) -> zero
//    bank conflicts (vectorized gathers are inherently 4-way conflicted).

#define ROW_DIM 592
#define RPB 4                                   // rows per block
#define NT 128                                  // threads per block
#define FLOATS_PER_BLOCK (ROW_DIM * RPB)        // 2368
#define VEC4_PER_BLOCK (FLOATS_PER_BLOCK / 4)   // 592

__device__ __forceinline__ int perm_src(int c) {
    if (c < 128) return c;
    if (c < 320) { int l = c - 128; return 128 + (l & 63) * 3 + (l >> 6); }
    if (c < 480) { int l = c - 320; return 320 + (l & 31) * 5 + (l >> 5); }
    { int l = c - 480; return 480 + (l & 15) * 7 + (l >> 4); }
}

__global__ __launch_bounds__(NT, 16)
void transpose_irreps_fine(const float* __restrict__ in, float* __restrict__ out) {
    __shared__ __align__(16) float smem[FLOATS_PER_BLOCK];

    const int tid = threadIdx.x;
    const long long block_elem_base = (long long)blockIdx.x * FLOATS_PER_BLOCK;

    // Phase 1: coalesced vectorized streaming loads of 4 rows into smem
    const float4* __restrict__ in4 = reinterpret_cast<const float4*>(in + block_elem_base);
    float4* __restrict__ sm4 = reinterpret_cast<float4*>(smem);
    #pragma unroll
    for (int i = tid; i < VEC4_PER_BLOCK; i += NT) {
        sm4[i] = __ldcs(in4 + i);
    }
    __syncthreads();

    // Phase 2: coalesced streaming stores; conflict-free smem gather
    float* __restrict__ out_base = out + block_elem_base;
    #pragma unroll
    for (int cb = 0; cb < ROW_DIM; cb += NT) {
        int c = cb + tid;
        if (c < ROW_DIM) {
            int s = perm_src(c);
            #pragma unroll
            for (int r = 0; r < RPB; r++) {
                __stcs(out_base + r * ROW_DIM + c, smem[r * ROW_DIM + s]);
            }
        }
    }
}

extern "C" void kernel_launch(void* const* d_in, const int* in_sizes, int n_in,
                              void* d_out, int out_size) {
    const float* x = (const float*)d_in[0];
    float* out = (float*)d_out;
    int n_rows = in_sizes[0] / ROW_DIM;     // 200000
    int grid = n_rows / RPB;                // 50000 (exact: 200000 % 4 == 0)
    transpose_irreps_fine<<<grid, NT>>>(x, out);
}

// round 13
// speedup vs baseline: 1.0107x; 1.0107x over previous
#include <cuda_runtime.h>
#include <stdint.h>

// TransposeIrrepsLayout: per-row segment transpose, segments (u,v) =
// (128,1),(64,3),(32,5),(16,7), row dim 592 fp32, 200000 rows.
// out[off + a*u + b] = in[off + b*v + a]
// For output column c: a = (c-off) >> log2(u), b = (c-off) & (u-1); src = off + b*v + a
//
// FINAL converged design — measured at the memory-system roofline:
// ~7.15 TB/s effective (89% of HBM3e spec), 85% dram__cycles_active,
// streaming-memcpy parity. Confirmed over 9 benches (one environmental
// outlier identified and excluded). Seven structural alternatives measured
// and rejected with attributed causes (pipelines -7..-10% DRAM; vector
// gathers bank-conflicted; direct gather 3.9x L1 amplification; identity
// bypass neutral).
//
//  - 4 rows staged per CTA in 9.5 KB smem -> 16 CTAs/SM, ~94% occupancy;
//    cross-CTA load/store phase mixing overlaps the read and write streams.
//  - Phase 1: float4 coalesced streaming loads (evict-first, touch-once).
//  - Phase 2: lane-consecutive output columns -> coalesced STG.32 streaming
//    stores; smem gather lane-stride = v in {1,3,5,7} (all odd) -> zero
//    bank conflicts.

#define ROW_DIM 592
#define RPB 4                                   // rows per block
#define NT 128                                  // threads per block
#define FLOATS_PER_BLOCK (ROW_DIM * RPB)        // 2368
#define VEC4_PER_BLOCK (FLOATS_PER_BLOCK / 4)   // 592

__device__ __forceinline__ int perm_src(int c) {
    if (c < 128) return c;
    if (c < 320) { int l = c - 128; return 128 + (l & 63) * 3 + (l >> 6); }
    if (c < 480) { int l = c - 320; return 320 + (l & 31) * 5 + (l >> 5); }
    { int l = c - 480; return 480 + (l & 15) * 7 + (l >> 4); }
}

__global__ __launch_bounds__(NT, 16)
void transpose_irreps_fine(const float* __restrict__ in, float* __restrict__ out) {
    __shared__ __align__(16) float smem[FLOATS_PER_BLOCK];

    const int tid = threadIdx.x;
    const long long block_elem_base = (long long)blockIdx.x * FLOATS_PER_BLOCK;

    // Phase 1: coalesced vectorized streaming loads of 4 rows into smem
    const float4* __restrict__ in4 = reinterpret_cast<const float4*>(in + block_elem_base);
    float4* __restrict__ sm4 = reinterpret_cast<float4*>(smem);
    #pragma unroll
    for (int i = tid; i < VEC4_PER_BLOCK; i += NT) {
        sm4[i] = __ldcs(in4 + i);
    }
    __syncthreads();

    // Phase 2: coalesced streaming stores; conflict-free smem gather
    float* __restrict__ out_base = out + block_elem_base;
    #pragma unroll
    for (int cb = 0; cb < ROW_DIM; cb += NT) {
        int c = cb + tid;
        if (c < ROW_DIM) {
            int s = perm_src(c);
            #pragma unroll
            for (int r = 0; r < RPB; r++) {
                __stcs(out_base + r * ROW_DIM + c, smem[r * ROW_DIM + s]);
            }
        }
    }
}

extern "C" void kernel_launch(void* const* d_in, const int* in_sizes, int n_in,
                              void* d_out, int out_size) {
    const float* x = (const float*)d_in[0];
    float* out = (float*)d_out;
    int n_rows = in_sizes[0] / ROW_DIM;     // 200000
    int grid = n_rows / RPB;                // 50000 (exact: 200000 % 4 == 0)
    transpose_irreps_fine<<<grid, NT>>>(x, out);
}